// round 15
// baseline (speedup 1.0000x reference)
#include <cuda_runtime.h>
#include <cuda_fp16.h>
#include <cstdint>
#include <math.h>

// ---------------- problem constants ----------------
#define TOKENS   131072      // 4 * 32 * 32 * 32
#define CDIM     64
#define KCODES   1024
#define HWD      32768
// out layout: [z_q (8388608) | loss | perplexity | indices (131072) | mean_dist]
#define LOSS_OFF 8388608
#define PERP_OFF 8388609
#define IDX_OFF  8388610
#define MEAN_OFF 8519682

typedef unsigned int u32;

// ---------------- global scratch (static, no allocs) ----------------
__device__ float g_e2[KCODES];          // ||e_k||^2 (raw, for exact re-rank)
__device__ float g_e2h[KCODES];         // 0.5*||e_k||^2 + 128 (MMA C-init for packed keys)
__device__ float g_esum[CDIM];          // sum_k e[k][c]
__device__ float g_zsum[CDIM];          // sum_n z[n][c]
__device__ float g_sz2;                 // sum all z^2
__device__ int   g_hist[KCODES];        // argmin bincount
__device__ u32   g_done;                // last-CTA counter (reset by last CTA)
// codebook fp16 in per-lane mma fragment order: [chunk8][sub8][q4][lane32][4xu32]
__device__ __align__(16) u32 g_Bf[65536];

// ---------------- helpers ----------------
__device__ __forceinline__ float warp_red(float v) {
#pragma unroll
    for (int o = 16; o; o >>= 1) v += __shfl_down_sync(0xffffffffu, v, o);
    return v;
}
__device__ __forceinline__ u32 pack_h2(float x0, float x1) {
    __half2 h = __halves2half2(__float2half_rn(x0), __float2half_rn(x1));
    return *reinterpret_cast<u32*>(&h);
}
// m16n8k16 row.col f16 -> f32, accumulate in place (HMMA)
__device__ __forceinline__ void mma16816(float d[4], const u32 a[4], u32 b0, u32 b1) {
    asm("mma.sync.aligned.m16n8k16.row.col.f32.f16.f16.f32 "
        "{%0,%1,%2,%3}, {%4,%5,%6,%7}, {%8,%9}, {%0,%1,%2,%3};"
        : "+f"(d[0]), "+f"(d[1]), "+f"(d[2]), "+f"(d[3])
        : "r"(a[0]), "r"(a[1]), "r"(a[2]), "r"(a[3]), "r"(b0), "r"(b1));
}
// first MMA of a chain: C = {c0, c1, c0, c1}, D written fresh
__device__ __forceinline__ void mma16816_c(float d[4], const u32 a[4], u32 b0, u32 b1,
                                           float c0, float c1) {
    asm("mma.sync.aligned.m16n8k16.row.col.f32.f16.f16.f32 "
        "{%0,%1,%2,%3}, {%4,%5,%6,%7}, {%8,%9}, {%10,%11,%10,%11};"
        : "=f"(d[0]), "=f"(d[1]), "=f"(d[2]), "=f"(d[3])
        : "r"(a[0]), "r"(a[1]), "r"(a[2]), "r"(a[3]), "r"(b0), "r"(b1),
          "f"(c0), "f"(c1));
}

// exact fp32 distance with ROUND-1 accumulation order (matches reference):
// 4 accumulators by channel mod 4, merged (A0+A1)+(A2+A3), dist = fma(-2, dot, e2)
__device__ __forceinline__ float exact_dist(const float* __restrict__ zcol, int apad,
                                            const float4* __restrict__ e4, int code) {
    float A0 = 0.0f, A1 = 0.0f, A2 = 0.0f, A3 = 0.0f;
#pragma unroll
    for (int c4 = 0; c4 < 16; c4++) {
        float4 e = __ldg(&e4[code * 16 + c4]);
        A0 = fmaf(zcol[(4 * c4 + 0) * apad], e.x, A0);
        A1 = fmaf(zcol[(4 * c4 + 1) * apad], e.y, A1);
        A2 = fmaf(zcol[(4 * c4 + 2) * apad], e.z, A2);
        A3 = fmaf(zcol[(4 * c4 + 3) * apad], e.w, A3);
    }
    float dot = (A0 + A1) + (A2 + A3);
    return fmaf(-2.0f, dot, g_e2[code]);
}

// ---------------- launch 1: fused prep (init + e2/e2h + esum + Bf layout) ----------------
// blocks 0..255: codebook -> fragment order; 256..259: e2; 260..323: esum; 324: init
__global__ void vq_prep(const float* __restrict__ emb) {
    int bi = blockIdx.x;
    int tid = threadIdx.x;
    if (bi < 256) {
        u32 u = bi * 256 + tid;
        u32 j = u & 3, l = (u >> 2) & 31, q = (u >> 7) & 3, s = (u >> 9) & 7, o = u >> 12;
        u32 g = l >> 2, t = l & 3, n = q >> 1, kp = q & 1, k = 2 * kp + (j >> 1), r = j & 1;
        u32 code = o * 128 + s * 16 + n * 8 + g;
        u32 ch   = k * 16 + 2 * t + 8 * r;
        const float* row = emb + code * CDIM + ch;
        g_Bf[u] = pack_h2(row[0], row[1]);
    } else if (bi < 260) {
        int k = (bi - 256) * 256 + tid;
        const float4* e4 = (const float4*)emb;
        float s = 0.0f;
#pragma unroll
        for (int j = 0; j < 16; j++) {
            float4 v = e4[k * 16 + j];
            s += v.x * v.x + v.y * v.y + v.z * v.z + v.w * v.w;
        }
        g_e2[k]  = s;
        g_e2h[k] = 0.5f * s + 128.0f;
    } else if (bi < 324) {
        int c = bi - 260;
        float s = 0.0f;
        for (int k = tid; k < KCODES; k += 256) s += emb[k * CDIM + c];
        s = warp_red(s);
        __shared__ float sw[8];
        if ((tid & 31) == 0) sw[tid >> 5] = s;
        __syncthreads();
        if (tid == 0) {
            float t2 = 0.0f;
            for (int w = 0; w < 8; w++) t2 += sw[w];
            g_esum[c] = t2;
        }
    } else {
#pragma unroll
        for (int i = 0; i < 4; i++) g_hist[tid + i * 256] = 0;
        if (tid < CDIM) g_zsum[tid] = 0.0f;
        if (tid == 0)   { g_sz2 = 0.0f; }
    }
}

// ---------------- launch 2: M=16/warp k-split hh-MMA + top-3 + re-rank + fused final ----
// 1024 CTAs x 256 threads; CTA = 128 tokens (8 warps x M=16), 8 x 128-code chunks. occ 3.
#define APADF 132                            // 16B-aligned rows, conflict-free frag build
#define SM_ZF   0
#define SM_B    33792                        // 64*132*4; 2 bufs x 16384
#define SM_E2   66560                        // 2 x 512 (biased half-e2)
#define SM_CAND 67584                        // 128 tokens x 3 x u32 = 1536
#define SM_S2   69120                        // 64
#define SMEM_TOTAL 69184

__global__ void __launch_bounds__(256, 3)
vq_main_mma(const float* __restrict__ z, const float* __restrict__ emb,
            float* __restrict__ out) {
    extern __shared__ __align__(16) char sm[];
    float* sh_zf   = (float*)(sm + SM_ZF);    // fp32 A tile [c][token], pad 132
    float* pS2     = (float*)(sm + SM_S2);
    u32*   sh_cand = (u32*)(sm + SM_CAND);    // [token][3] packed (dist'|code)

    const int tid = threadIdx.x;
    const int w = tid >> 5, l = tid & 31, g = l >> 2, t = l & 3;
    const int n0 = blockIdx.x * 128;
    const int b = n0 >> 15, hwb = n0 & 32767;
    const int tok  = tid & 127;
    const int half = tid >> 7;

    const u32 bB  = (u32)__cvta_generic_to_shared(sm + SM_B);
    const u32 bE2 = (u32)__cvta_generic_to_shared(sm + SM_E2);

#define COPY_B(o, buf) do {                                                       \
        _Pragma("unroll")                                                         \
        for (int j = 0; j < 4; j++) {                                             \
            int f = tid + 256 * j;                                                \
            const float4* src = ((const float4*)g_Bf) + (o) * 1024 + f;           \
            u32 dst = bB + (buf) * 16384 + f * 16;                                \
            asm volatile("cp.async.cg.shared.global [%0], [%1], 16;"              \
                         :: "r"(dst), "l"(src));                                  \
        }                                                                         \
        if (tid < 128) {                                                          \
            u32 de = bE2 + (buf) * 512 + tid * 4;                                 \
            asm volatile("cp.async.ca.shared.global [%0], [%1], 4;"               \
                         :: "r"(de), "l"(g_e2h + (o) * 128 + tid));               \
        }                                                                         \
        asm volatile("cp.async.commit_group;");                                   \
    } while (0)

    COPY_B(0, 0);

    // ---- A load: 128 tokens x 64 ch (each thread: 32 channels of one token) ----
    const float* zp = z + (size_t)b * CDIM * HWD + hwb + tok;
    float s2 = 0.0f;
#pragma unroll
    for (int i = 0; i < 32; i++) {
        int c = half * 32 + i;
        float x = zp[(size_t)c * HWD];
        sh_zf[c * APADF + tok] = x;
        s2 = fmaf(x, x, s2);
    }
    s2 = warp_red(s2);
    if (l == 0) pS2[w] = s2;
    __syncthreads();
    if (tid == 0) {
        float v = 0.0f;
        for (int i = 0; i < 8; i++) v += pS2[i];
        atomicAdd(&g_sz2, v);
    }
    // per-channel z sums (vectorized float4 from smem): 4 threads per channel
    {
        int c = tid >> 2, q = tid & 3;
        const float4* pz = (const float4*)(sh_zf + c * APADF + q * 32);
        float s = 0.0f;
#pragma unroll
        for (int i = 0; i < 8; i++) {
            float4 v = pz[i];
            s += (v.x + v.y) + (v.z + v.w);
        }
        atomicAdd(&g_zsum[c], s);
    }

    // ---- build A fragments = fp16(-z), M=16 per warp (16 regs) ----
    u32 a_h[4][4];
    const int wb = w * 16;
    const int r0 = wb + g;
#pragma unroll
    for (int k = 0; k < 4; k++) {
        int c0 = k * 16 + 2 * t;
        a_h[k][0] = pack_h2(-sh_zf[c0 * APADF + r0],           -sh_zf[(c0 + 1) * APADF + r0]);
        a_h[k][1] = pack_h2(-sh_zf[c0 * APADF + r0 + 8],       -sh_zf[(c0 + 1) * APADF + r0 + 8]);
        a_h[k][2] = pack_h2(-sh_zf[(c0 + 8) * APADF + r0],     -sh_zf[(c0 + 9) * APADF + r0]);
        a_h[k][3] = pack_h2(-sh_zf[(c0 + 8) * APADF + r0 + 8], -sh_zf[(c0 + 9) * APADF + r0 + 8]);
    }

    // per-chain sorted top-3 packed keys (2 chains: rows r0, r0+8)
    u32 K0a[2], K1a[2], K2a[2];
#pragma unroll
    for (int s = 0; s < 2; s++) { K0a[s] = K1a[s] = K2a[s] = 0xFFFFFFFFu; }
#define MKKEY(d, c) ((__float_as_uint(d) & 0xFFFFFC00u) | (u32)(c))
    // sorted top-3 of quad (9 IMNMX) + merge sorted triples (9 IMNMX)
#define QUAD3(s, k0, k1, k2, k3) do {                                          \
        u32 _m0 = min((k0), (k1)), _M0 = max((k0), (k1));                      \
        u32 _m1 = min((k2), (k3)), _M1 = max((k2), (k3));                      \
        u32 _t0 = min(_m0, _m1);                                               \
        u32 _x  = max(_m0, _m1), _y = min(_M0, _M1);                           \
        u32 _t1 = min(_x, _y),  _t2 = max(_x, _y);                             \
        u32 _r0 = min(K0a[s], _t0), _mm = max(K0a[s], _t0);                    \
        u32 _c1 = min(K1a[s], _t1), _c1x = max(K1a[s], _t1);                   \
        u32 _r1 = min(_mm, _c1);                                               \
        u32 _r2 = min(max(_mm, _c1), min(_c1x, min(K2a[s], _t2)));             \
        K0a[s] = _r0; K1a[s] = _r1; K2a[s] = _r2;                              \
    } while (0)

    // ---- main loop: 8 chunks of 128 codes, double-buffered cp.async ----
#pragma unroll 1
    for (int o = 0; o < 8; o++) {
        asm volatile("cp.async.wait_group 0;" ::: "memory");
        __syncthreads();
        if (o < 7) COPY_B(o + 1, (o + 1) & 1);

        const char*  bbase = sm + SM_B + (o & 1) * 16384;
        const float* e2p   = (const float*)(sm + SM_E2 + (o & 1) * 512);
        const uint4* bq    = (const uint4*)(bbase + l * 16);

        // fully unrolled: ptxas pipelines LDS across subs
#pragma unroll
        for (int sub = 0; sub < 8; sub++) {           // 16 codes per sub
            const uint4* bp = bq + sub * 128;
            uint4 q0 = bp[0];     // n=0, k=0..1
            uint4 q1 = bp[32];    // n=0, k=2..3
            uint4 q2 = bp[64];    // n=1, k=0..1
            uint4 q3 = bp[96];    // n=1, k=2..3
            float2 e0 = *(const float2*)(e2p + sub * 16 + 2 * t);        // codes cc, cc+1
            float2 e1 = *(const float2*)(e2p + sub * 16 + 8 + 2 * t);    // codes cc+8, cc+9

            // k-split: Da = e2h - dot(k lo half), Db = -dot(k hi half); 2-deep chains
            float Da[2][4], Db[2][4];
            mma16816_c(Da[0], a_h[0], q0.x, q0.y, e0.x, e0.y);
            mma16816_c(Db[0], a_h[1], q0.z, q0.w, 0.0f, 0.0f);
            mma16816  (Da[0], a_h[2], q1.x, q1.y);
            mma16816  (Db[0], a_h[3], q1.z, q1.w);
            mma16816_c(Da[1], a_h[0], q2.x, q2.y, e1.x, e1.y);
            mma16816_c(Db[1], a_h[1], q2.z, q2.w, 0.0f, 0.0f);
            mma16816  (Da[1], a_h[2], q3.x, q3.y);
            mma16816  (Db[1], a_h[3], q3.z, q3.w);

            int cc = o * 128 + sub * 16 + 2 * t;
            float d00 = Da[0][0] + Db[0][0], d01 = Da[0][1] + Db[0][1];
            float d02 = Da[0][2] + Db[0][2], d03 = Da[0][3] + Db[0][3];
            float d10 = Da[1][0] + Db[1][0], d11 = Da[1][1] + Db[1][1];
            float d12 = Da[1][2] + Db[1][2], d13 = Da[1][3] + Db[1][3];
            QUAD3(0, MKKEY(d00, cc),     MKKEY(d01, cc + 1),
                     MKKEY(d10, cc + 8), MKKEY(d11, cc + 9));
            QUAD3(1, MKKEY(d02, cc),     MKKEY(d03, cc + 1),
                     MKKEY(d12, cc + 8), MKKEY(d13, cc + 9));
        }
    }

    // ---- quad merge: per chain, merge 4 lanes' sorted top-3 (u32 keys) ----
#pragma unroll
    for (int s = 0; s < 2; s++) {
        u32 K0 = K0a[s], K1 = K1a[s], K2 = K2a[s];
#pragma unroll
        for (int off = 1; off <= 2; off <<= 1) {
            u32 OA = __shfl_xor_sync(0xffffffffu, K0, off);
            u32 OB = __shfl_xor_sync(0xffffffffu, K1, off);
            u32 OC = __shfl_xor_sync(0xffffffffu, K2, off);
            u32 r0v = min(K0, OA);
            u32 m   = max(K0, OA);
            u32 c1  = min(K1, OB);
            u32 c1x = max(K1, OB);
            u32 r1v = min(m, c1);
            u32 r2v = min(max(m, c1), min(c1x, min(K2, OC)));
            K0 = r0v; K1 = r1v; K2 = r2v;
        }
        if (t == 0) {
            int tk = wb + s * 8 + g;
            sh_cand[tk * 3 + 0] = K0;
            sh_cand[tk * 3 + 1] = K1;
            sh_cand[tk * 3 + 2] = K2;
        }
    }
    __syncthreads();

    // ---- per-token (tid<128): gate on approx gap, exact fp32 re-rank of top-3 ----
    const float4* e4 = (const float4*)emb;
    if (tid < 128) {
        u32 K0 = sh_cand[tid * 3 + 0];
        u32 K1 = sh_cand[tid * 3 + 1];
        u32 K2 = sh_cand[tid * 3 + 2];
        int idx = (int)(K0 & 1023u);
        float ad0 = __uint_as_float(K0 & 0xFFFFFC00u);
        float ad1 = __uint_as_float(K1 & 0xFFFFFC00u);
        if (ad1 - ad0 < 0.08f) {
            int j1 = (int)(K1 & 1023u);
            int j2 = (int)(K2 & 1023u);
            float eA = exact_dist(sh_zf + tid, APADF, e4, idx);
            float eB = exact_dist(sh_zf + tid, APADF, e4, j1);
            float eC = exact_dist(sh_zf + tid, APADF, e4, j2);
            if (eB < eA || (eB == eA && j1 < idx)) { eA = eB; idx = j1; }
            if (eC < eA || (eC == eA && j2 < idx)) { idx = j2; }
        }
        sh_cand[tid * 3] = (u32)idx;        // publish final index
        out[IDX_OFF + n0 + tid] = (float)idx;
        atomicAdd(&g_hist[idx], 1);
    }
    __syncthreads();

    // ---- coalesced z_q gather: all 256 threads, 8 float4 each ----
    {
        int idx = (int)sh_cand[tok * 3];
        float* ob = out + (size_t)b * CDIM * HWD + hwb + tok;
#pragma unroll
        for (int j = 0; j < 8; j++) {
            int c4 = half * 8 + j;
            float4 v = __ldg(&e4[idx * 16 + c4]);
            ob[(size_t)(4 * c4 + 0) * HWD] = v.x;
            ob[(size_t)(4 * c4 + 1) * HWD] = v.y;
            ob[(size_t)(4 * c4 + 2) * HWD] = v.z;
            ob[(size_t)(4 * c4 + 3) * HWD] = v.w;
        }
    }

    // ---- fused finalize: last CTA computes perplexity + analytic mean(dist) ----
    __threadfence();
    __shared__ u32 amLast;
    if (tid == 0) amLast = (atomicAdd(&g_done, 1) == (u32)(gridDim.x - 1)) ? 1u : 0u;
    __syncthreads();
    if (amLast) {
        if (tid == 0) g_done = 0;   // reset for next graph replay
        double e2s = 0.0, ent = 0.0;
#pragma unroll
        for (int i = 0; i < 4; i++) {
            int k = tid + i * 256;
            e2s += (double)g_e2[k];
            double h = (double)g_hist[k] * (1.0 / (double)TOKENS);
            ent += -h * log(h + 1e-10);
        }
        double dss = (tid < CDIM) ? (double)g_zsum[tid] * (double)g_esum[tid] : 0.0;
        __shared__ double d1[8], d2[8], d3[8];
#pragma unroll
        for (int o = 16; o; o >>= 1) {
            e2s += __shfl_down_sync(0xffffffffu, e2s, o);
            ent += __shfl_down_sync(0xffffffffu, ent, o);
            dss += __shfl_down_sync(0xffffffffu, dss, o);
        }
        if (l == 0) { d1[w] = e2s; d2[w] = ent; d3[w] = dss; }
        __syncthreads();
        if (tid == 0) {
            double E2 = 0, EN = 0, DS = 0;
            for (int i = 0; i < 8; i++) { E2 += d1[i]; EN += d2[i]; DS += d3[i]; }
            out[LOSS_OFF] = 0.0f;
            out[PERP_OFF] = (float)exp(EN);
            double nt = (double)TOKENS, kk = (double)KCODES;
            out[MEAN_OFF] = (float)((kk * (double)g_sz2 - 2.0 * DS + nt * E2) / (nt * kk));
        }
    }
#undef COPY_B
#undef QUAD3
#undef MKKEY
}

extern "C" void kernel_launch(void* const* d_in, const int* in_sizes, int n_in,
                              void* d_out, int out_size) {
    (void)in_sizes; (void)n_in; (void)out_size;
    const float* z   = (const float*)d_in[0];
    const float* emb = (const float*)d_in[1];
    float* out = (float*)d_out;

    cudaFuncSetAttribute(vq_main_mma, cudaFuncAttributeMaxDynamicSharedMemorySize, SMEM_TOTAL);

    vq_prep    <<<325,  256 >>>(emb);                    // 1 (fused init+e2+esum+Bf)
    vq_main_mma<<<1024, 256, SMEM_TOTAL>>>(z, emb, out); // 2 (+ fused finalize)
}

// round 16
// speedup vs baseline: 1.0550x; 1.0550x over previous
#include <cuda_runtime.h>
#include <cuda_fp16.h>
#include <cstdint>
#include <math.h>

// ---------------- problem constants ----------------
#define TOKENS   131072      // 4 * 32 * 32 * 32
#define CDIM     64
#define KCODES   1024
#define HWD      32768
// out layout: [z_q (8388608) | loss | perplexity | indices (131072) | mean_dist]
#define LOSS_OFF 8388608
#define PERP_OFF 8388609
#define IDX_OFF  8388610
#define MEAN_OFF 8519682

typedef unsigned int u32;

// ---------------- global scratch (static, no allocs) ----------------
__device__ float g_e2[KCODES];          // ||e_k||^2 (raw, for exact re-rank)
__device__ float g_e2h[KCODES];         // 0.5*||e_k||^2 + 128 (MMA C-init for packed keys)
__device__ float g_esum[CDIM];          // sum_k e[k][c]
__device__ float g_zsum[CDIM];          // sum_n z[n][c]
__device__ float g_sz2;                 // sum all z^2
__device__ int   g_hist[KCODES];        // argmin bincount
__device__ u32   g_done;                // last-CTA counter (reset by last CTA)
// codebook fp16 in per-lane mma fragment order: [chunk8][sub8][q4][lane32][4xu32]
__device__ __align__(16) u32 g_Bf[65536];

// ---------------- helpers ----------------
__device__ __forceinline__ float warp_red(float v) {
#pragma unroll
    for (int o = 16; o; o >>= 1) v += __shfl_down_sync(0xffffffffu, v, o);
    return v;
}
__device__ __forceinline__ u32 pack_h2(float x0, float x1) {
    __half2 h = __halves2half2(__float2half_rn(x0), __float2half_rn(x1));
    return *reinterpret_cast<u32*>(&h);
}
// m16n8k16 row.col f16 -> f32, accumulate in place (HMMA)
__device__ __forceinline__ void mma16816(float d[4], const u32 a[4], u32 b0, u32 b1) {
    asm("mma.sync.aligned.m16n8k16.row.col.f32.f16.f16.f32 "
        "{%0,%1,%2,%3}, {%4,%5,%6,%7}, {%8,%9}, {%0,%1,%2,%3};"
        : "+f"(d[0]), "+f"(d[1]), "+f"(d[2]), "+f"(d[3])
        : "r"(a[0]), "r"(a[1]), "r"(a[2]), "r"(a[3]), "r"(b0), "r"(b1));
}
// first MMA of a chain: C = {c0, c1, c0, c1}, D written fresh
__device__ __forceinline__ void mma16816_c(float d[4], const u32 a[4], u32 b0, u32 b1,
                                           float c0, float c1) {
    asm("mma.sync.aligned.m16n8k16.row.col.f32.f16.f16.f32 "
        "{%0,%1,%2,%3}, {%4,%5,%6,%7}, {%8,%9}, {%10,%11,%10,%11};"
        : "=f"(d[0]), "=f"(d[1]), "=f"(d[2]), "=f"(d[3])
        : "r"(a[0]), "r"(a[1]), "r"(a[2]), "r"(a[3]), "r"(b0), "r"(b1),
          "f"(c0), "f"(c1));
}

// exact fp32 distance with ROUND-1 accumulation order (matches reference):
// 4 accumulators by channel mod 4, merged (A0+A1)+(A2+A3), dist = fma(-2, dot, e2)
__device__ __forceinline__ float exact_dist(const float* __restrict__ zcol, int apad,
                                            const float4* __restrict__ e4, int code) {
    float A0 = 0.0f, A1 = 0.0f, A2 = 0.0f, A3 = 0.0f;
#pragma unroll
    for (int c4 = 0; c4 < 16; c4++) {
        float4 e = __ldg(&e4[code * 16 + c4]);
        A0 = fmaf(zcol[(4 * c4 + 0) * apad], e.x, A0);
        A1 = fmaf(zcol[(4 * c4 + 1) * apad], e.y, A1);
        A2 = fmaf(zcol[(4 * c4 + 2) * apad], e.z, A2);
        A3 = fmaf(zcol[(4 * c4 + 3) * apad], e.w, A3);
    }
    float dot = (A0 + A1) + (A2 + A3);
    return fmaf(-2.0f, dot, g_e2[code]);
}

// ---------------- launch 1: fused prep (init + e2/e2h + esum + Bf layout) ----------------
// blocks 0..255: codebook -> fragment order; 256..259: e2; 260..323: esum; 324: init
__global__ void vq_prep(const float* __restrict__ emb) {
    int bi = blockIdx.x;
    int tid = threadIdx.x;
    if (bi < 256) {
        u32 u = bi * 256 + tid;
        u32 j = u & 3, l = (u >> 2) & 31, q = (u >> 7) & 3, s = (u >> 9) & 7, o = u >> 12;
        u32 g = l >> 2, t = l & 3, n = q >> 1, kp = q & 1, k = 2 * kp + (j >> 1), r = j & 1;
        u32 code = o * 128 + s * 16 + n * 8 + g;
        u32 ch   = k * 16 + 2 * t + 8 * r;
        const float* row = emb + code * CDIM + ch;
        g_Bf[u] = pack_h2(row[0], row[1]);
    } else if (bi < 260) {
        int k = (bi - 256) * 256 + tid;
        const float4* e4 = (const float4*)emb;
        float s = 0.0f;
#pragma unroll
        for (int j = 0; j < 16; j++) {
            float4 v = e4[k * 16 + j];
            s += v.x * v.x + v.y * v.y + v.z * v.z + v.w * v.w;
        }
        g_e2[k]  = s;
        g_e2h[k] = 0.5f * s + 128.0f;
    } else if (bi < 324) {
        int c = bi - 260;
        float s = 0.0f;
        for (int k = tid; k < KCODES; k += 256) s += emb[k * CDIM + c];
        s = warp_red(s);
        __shared__ float sw[8];
        if ((tid & 31) == 0) sw[tid >> 5] = s;
        __syncthreads();
        if (tid == 0) {
            float t2 = 0.0f;
            for (int w = 0; w < 8; w++) t2 += sw[w];
            g_esum[c] = t2;
        }
    } else {
#pragma unroll
        for (int i = 0; i < 4; i++) g_hist[tid + i * 256] = 0;
        if (tid < CDIM) g_zsum[tid] = 0.0f;
        if (tid == 0)   { g_sz2 = 0.0f; }
    }
}

// ---------------- launch 2: M=32/warp k-split hh-MMA + hybrid-pipe top-3 + re-rank ----
// 512 CTAs x 256 threads; CTA = 256 tokens (8 warps x M=32), 8 x 128-code chunks. occ 2.
#define APADF 260                            // 16B-aligned rows, conflict-free frag build
#define SM_ZF   0
#define SM_B    66560                        // 64*260*4; 2 bufs x 16384
#define SM_E2   99328                        // 2 x 512 (biased half-e2)
#define SM_CAND 100352                       // 256 tokens x 3 x u32 = 3072
#define SM_S2   103424                       // 64
#define SMEM_TOTAL 103488

__global__ void __launch_bounds__(256, 2)
vq_main_mma(const float* __restrict__ z, const float* __restrict__ emb,
            float* __restrict__ out) {
    extern __shared__ __align__(16) char sm[];
    float* sh_zf   = (float*)(sm + SM_ZF);    // fp32 A tile [c][token], pad 260
    float* pS2     = (float*)(sm + SM_S2);
    u32*   sh_cand = (u32*)(sm + SM_CAND);    // [token][3] packed (dist'|code)

    const int tid = threadIdx.x;
    const int w = tid >> 5, l = tid & 31, g = l >> 2, t = l & 3;
    const int n0 = blockIdx.x * 256;
    const int b = n0 >> 15, hwb = n0 & 32767;

    const u32 bB  = (u32)__cvta_generic_to_shared(sm + SM_B);
    const u32 bE2 = (u32)__cvta_generic_to_shared(sm + SM_E2);

#define COPY_B(o, buf) do {                                                       \
        _Pragma("unroll")                                                         \
        for (int j = 0; j < 4; j++) {                                             \
            int f = tid + 256 * j;                                                \
            const float4* src = ((const float4*)g_Bf) + (o) * 1024 + f;           \
            u32 dst = bB + (buf) * 16384 + f * 16;                                \
            asm volatile("cp.async.cg.shared.global [%0], [%1], 16;"              \
                         :: "r"(dst), "l"(src));                                  \
        }                                                                         \
        if (tid < 128) {                                                          \
            u32 de = bE2 + (buf) * 512 + tid * 4;                                 \
            asm volatile("cp.async.ca.shared.global [%0], [%1], 4;"               \
                         :: "r"(de), "l"(g_e2h + (o) * 128 + tid));               \
        }                                                                         \
        asm volatile("cp.async.commit_group;");                                   \
    } while (0)

    COPY_B(0, 0);

    // ---- A load: 256 tokens x 64 ch, fp32 into smem, fold z^2 ----
    const float* zp = z + (size_t)b * CDIM * HWD + hwb + tid;
    float s2 = 0.0f;
#pragma unroll
    for (int c = 0; c < 64; c++) {
        float x = zp[(size_t)c * HWD];
        sh_zf[c * APADF + tid] = x;
        s2 = fmaf(x, x, s2);
    }
    s2 = warp_red(s2);
    if (l == 0) pS2[w] = s2;
    __syncthreads();
    if (tid == 0) {
        float v = 0.0f;
        for (int i = 0; i < 8; i++) v += pS2[i];
        atomicAdd(&g_sz2, v);
    }
    // per-channel z sums (vectorized float4 from smem): 4 threads per channel
    {
        int c = tid >> 2, q = tid & 3;
        const float4* pz = (const float4*)(sh_zf + c * APADF + q * 64);
        float s = 0.0f;
#pragma unroll
        for (int i = 0; i < 16; i++) {
            float4 v = pz[i];
            s += (v.x + v.y) + (v.z + v.w);
        }
        atomicAdd(&g_zsum[c], s);
    }

    // ---- build A fragments = fp16(-z), M=32 per warp (32 regs) ----
    u32 a_h[2][4][4];
    const int wb = w * 32;
#pragma unroll
    for (int m = 0; m < 2; m++) {
        int r0 = wb + m * 16 + g;
#pragma unroll
        for (int k = 0; k < 4; k++) {
            int c0 = k * 16 + 2 * t;
            a_h[m][k][0] = pack_h2(-sh_zf[c0 * APADF + r0],           -sh_zf[(c0 + 1) * APADF + r0]);
            a_h[m][k][1] = pack_h2(-sh_zf[c0 * APADF + r0 + 8],       -sh_zf[(c0 + 1) * APADF + r0 + 8]);
            a_h[m][k][2] = pack_h2(-sh_zf[(c0 + 8) * APADF + r0],     -sh_zf[(c0 + 9) * APADF + r0]);
            a_h[m][k][3] = pack_h2(-sh_zf[(c0 + 8) * APADF + r0 + 8], -sh_zf[(c0 + 9) * APADF + r0 + 8]);
        }
    }

    // per-chain sorted top-3 packed keys (4 chains: m*2 + row-half)
    u32 K0a[4], K1a[4], K2a[4];
#pragma unroll
    for (int s = 0; s < 4; s++) { K0a[s] = K1a[s] = K2a[s] = 0xFFFFFFFFu; }
#define MKKEY(d, c) ((__float_as_uint(d) & 0xFFFFFC00u) | (u32)(c))
    // hybrid-pipe sorted top-3: quad-sort of new keys in fp32 (FMNMX, fma pipe) --
    // keys are positive floats so fp32 ordering == u32 ordering -- then merge into
    // the running sorted-3 in u32 (IMNMX, alu pipe). Balances both SMSP pipes.
#define QUAD3(s, k0, k1, k2, k3) do {                                          \
        float _f0 = __uint_as_float(k0), _f1 = __uint_as_float(k1);            \
        float _f2 = __uint_as_float(k2), _f3 = __uint_as_float(k3);            \
        float _m0 = fminf(_f0, _f1), _M0 = fmaxf(_f0, _f1);                    \
        float _m1 = fminf(_f2, _f3), _M1 = fmaxf(_f2, _f3);                    \
        float _t0 = fminf(_m0, _m1);                                           \
        float _x  = fmaxf(_m0, _m1), _y = fminf(_M0, _M1);                     \
        float _t1 = fminf(_x, _y),  _t2 = fmaxf(_x, _y);                       \
        u32 _u0 = __float_as_uint(_t0);                                        \
        u32 _u1 = __float_as_uint(_t1);                                        \
        u32 _u2 = __float_as_uint(_t2);                                        \
        u32 _r0 = min(K0a[s], _u0), _mm = max(K0a[s], _u0);                    \
        u32 _c1 = min(K1a[s], _u1), _c1x = max(K1a[s], _u1);                   \
        u32 _r1 = min(_mm, _c1);                                               \
        u32 _r2 = min(max(_mm, _c1), min(_c1x, min(K2a[s], _u2)));             \
        K0a[s] = _r0; K1a[s] = _r1; K2a[s] = _r2;                              \
    } while (0)

    // ---- main loop: 8 chunks of 128 codes, double-buffered cp.async ----
#pragma unroll 1
    for (int o = 0; o < 8; o++) {
        asm volatile("cp.async.wait_group 0;" ::: "memory");
        __syncthreads();
        if (o < 7) COPY_B(o + 1, (o + 1) & 1);

        const char*  bbase = sm + SM_B + (o & 1) * 16384;
        const float* e2p   = (const float*)(sm + SM_E2 + (o & 1) * 512);
        const uint4* bq    = (const uint4*)(bbase + l * 16);

        // fully unrolled: ptxas pipelines LDS across subs; B regs reused by both m-halves
#pragma unroll
        for (int sub = 0; sub < 8; sub++) {           // 16 codes per sub, 32 tokens per warp
            const uint4* bp = bq + sub * 128;
            uint4 q0 = bp[0];     // n=0, k=0..1
            uint4 q1 = bp[32];    // n=0, k=2..3
            uint4 q2 = bp[64];    // n=1, k=0..1
            uint4 q3 = bp[96];    // n=1, k=2..3
            float2 e0 = *(const float2*)(e2p + sub * 16 + 2 * t);        // codes cc, cc+1
            float2 e1 = *(const float2*)(e2p + sub * 16 + 8 + 2 * t);    // codes cc+8, cc+9
            int cc = o * 128 + sub * 16 + 2 * t;

#pragma unroll
            for (int m = 0; m < 2; m++) {
                // k-split: Da = e2h - dot(k lo half), Db = -dot(k hi half); 2-deep chains
                float Da[2][4], Db[2][4];
                mma16816_c(Da[0], a_h[m][0], q0.x, q0.y, e0.x, e0.y);
                mma16816_c(Db[0], a_h[m][1], q0.z, q0.w, 0.0f, 0.0f);
                mma16816  (Da[0], a_h[m][2], q1.x, q1.y);
                mma16816  (Db[0], a_h[m][3], q1.z, q1.w);
                mma16816_c(Da[1], a_h[m][0], q2.x, q2.y, e1.x, e1.y);
                mma16816_c(Db[1], a_h[m][1], q2.z, q2.w, 0.0f, 0.0f);
                mma16816  (Da[1], a_h[m][2], q3.x, q3.y);
                mma16816  (Db[1], a_h[m][3], q3.z, q3.w);

                float d00 = Da[0][0] + Db[0][0], d01 = Da[0][1] + Db[0][1];
                float d02 = Da[0][2] + Db[0][2], d03 = Da[0][3] + Db[0][3];
                float d10 = Da[1][0] + Db[1][0], d11 = Da[1][1] + Db[1][1];
                float d12 = Da[1][2] + Db[1][2], d13 = Da[1][3] + Db[1][3];
                QUAD3(m * 2,     MKKEY(d00, cc),     MKKEY(d01, cc + 1),
                                 MKKEY(d10, cc + 8), MKKEY(d11, cc + 9));
                QUAD3(m * 2 + 1, MKKEY(d02, cc),     MKKEY(d03, cc + 1),
                                 MKKEY(d12, cc + 8), MKKEY(d13, cc + 9));
            }
        }
    }

    // ---- quad merge: per chain, merge 4 lanes' sorted top-3 (u32 keys) ----
#pragma unroll
    for (int s = 0; s < 4; s++) {
        u32 K0 = K0a[s], K1 = K1a[s], K2 = K2a[s];
#pragma unroll
        for (int off = 1; off <= 2; off <<= 1) {
            u32 OA = __shfl_xor_sync(0xffffffffu, K0, off);
            u32 OB = __shfl_xor_sync(0xffffffffu, K1, off);
            u32 OC = __shfl_xor_sync(0xffffffffu, K2, off);
            u32 r0v = min(K0, OA);
            u32 m   = max(K0, OA);
            u32 c1  = min(K1, OB);
            u32 c1x = max(K1, OB);
            u32 r1v = min(m, c1);
            u32 r2v = min(max(m, c1), min(c1x, min(K2, OC)));
            K0 = r0v; K1 = r1v; K2 = r2v;
        }
        if (t == 0) {
            int tk = wb + (s >> 1) * 16 + (s & 1) * 8 + g;
            sh_cand[tk * 3 + 0] = K0;
            sh_cand[tk * 3 + 1] = K1;
            sh_cand[tk * 3 + 2] = K2;
        }
    }
    __syncthreads();

    // ---- per-token: gate on approx gap, exact fp32 re-rank of top-3 if close ----
    const float4* e4 = (const float4*)emb;
    u32 K0 = sh_cand[tid * 3 + 0];
    u32 K1 = sh_cand[tid * 3 + 1];
    u32 K2 = sh_cand[tid * 3 + 2];
    int idx = (int)(K0 & 1023u);
    float ad0 = __uint_as_float(K0 & 0xFFFFFC00u);
    float ad1 = __uint_as_float(K1 & 0xFFFFFC00u);
    if (ad1 - ad0 < 0.08f) {
        int j1 = (int)(K1 & 1023u);
        int j2 = (int)(K2 & 1023u);
        float eA = exact_dist(sh_zf + tid, APADF, e4, idx);
        float eB = exact_dist(sh_zf + tid, APADF, e4, j1);
        float eC = exact_dist(sh_zf + tid, APADF, e4, j2);
        if (eB < eA || (eB == eA && j1 < idx)) { eA = eB; idx = j1; }
        if (eC < eA || (eC == eA && j2 < idx)) { idx = j2; }
    }

    // ---- per-token outputs: index, histogram, coalesced z_q gather ----
    out[IDX_OFF + n0 + tid] = (float)idx;
    atomicAdd(&g_hist[idx], 1);

    float* ob = out + (size_t)b * CDIM * HWD + hwb + tid;
#pragma unroll
    for (int j = 0; j < 16; j++) {
        float4 v = __ldg(&e4[idx * 16 + j]);
        ob[(size_t)(4 * j + 0) * HWD] = v.x;
        ob[(size_t)(4 * j + 1) * HWD] = v.y;
        ob[(size_t)(4 * j + 2) * HWD] = v.z;
        ob[(size_t)(4 * j + 3) * HWD] = v.w;
    }

    // ---- fused finalize: last CTA computes perplexity + analytic mean(dist) ----
    __threadfence();
    __shared__ u32 amLast;
    if (tid == 0) amLast = (atomicAdd(&g_done, 1) == (u32)(gridDim.x - 1)) ? 1u : 0u;
    __syncthreads();
    if (amLast) {
        if (tid == 0) g_done = 0;   // reset for next graph replay
        double e2s = 0.0, ent = 0.0;
#pragma unroll
        for (int i = 0; i < 4; i++) {
            int k = tid + i * 256;
            e2s += (double)g_e2[k];
            double h = (double)g_hist[k] * (1.0 / (double)TOKENS);
            ent += -h * log(h + 1e-10);
        }
        double dss = (tid < CDIM) ? (double)g_zsum[tid] * (double)g_esum[tid] : 0.0;
        __shared__ double d1[8], d2[8], d3[8];
#pragma unroll
        for (int o = 16; o; o >>= 1) {
            e2s += __shfl_down_sync(0xffffffffu, e2s, o);
            ent += __shfl_down_sync(0xffffffffu, ent, o);
            dss += __shfl_down_sync(0xffffffffu, dss, o);
        }
        if (l == 0) { d1[w] = e2s; d2[w] = ent; d3[w] = dss; }
        __syncthreads();
        if (tid == 0) {
            double E2 = 0, EN = 0, DS = 0;
            for (int i = 0; i < 8; i++) { E2 += d1[i]; EN += d2[i]; DS += d3[i]; }
            out[LOSS_OFF] = 0.0f;
            out[PERP_OFF] = (float)exp(EN);
            double nt = (double)TOKENS, kk = (double)KCODES;
            out[MEAN_OFF] = (float)((kk * (double)g_sz2 - 2.0 * DS + nt * E2) / (nt * kk));
        }
    }
#undef COPY_B
#undef QUAD3
#undef MKKEY
}

extern "C" void kernel_launch(void* const* d_in, const int* in_sizes, int n_in,
                              void* d_out, int out_size) {
    (void)in_sizes; (void)n_in; (void)out_size;
    const float* z   = (const float*)d_in[0];
    const float* emb = (const float*)d_in[1];
    float* out = (float*)d_out;

    cudaFuncSetAttribute(vq_main_mma, cudaFuncAttributeMaxDynamicSharedMemorySize, SMEM_TOTAL);

    vq_prep    <<<325, 256 >>>(emb);                    // 1 (fused init+e2+esum+Bf)
    vq_main_mma<<<512, 256, SMEM_TOTAL>>>(z, emb, out); // 2 (+ fused finalize)
}